// round 4
// baseline (speedup 1.0000x reference)
#include <cuda_runtime.h>

#define BB   4
#define NA   2048
#define NBB  2048
#define HH   8
#define LOG2E 1.44269504088896340736f

typedef unsigned long long ull;

#define FMA2(d, a, b) asm("fma.rn.f32x2 %0, %1, %2, %0;" : "+l"(d) : "l"(a), "l"(b))
#define PACK2(d, lo, hi) asm("mov.b64 %0, {%1, %2};" : "=l"(d) : "f"(lo), "f"(hi))
#define UNPACK2(lo, hi, s) asm("mov.b64 {%0, %1}, %2;" : "=f"(lo), "=f"(hi) : "l"(s))

// ---------------- scratch (static device allocs only) ----------------
__device__ float g_zB[BB * NBB * 128];   // (b, m, h*16+d)
__device__ float g_eA[BB * NA * HH];     // (b*NA+n)*8 + h   (pre-scaled by LOG2E)
__device__ float g_eB[BB * HH * NBB];    // (b*8+h)*2048 + m (pre-scaled by LOG2E)
__device__ float g_WT[128 * 128];        // W_T[c*128+o] = W_w[o*128+c]

// ---------------- K0: transpose W (wide, no serial bottleneck) ----------------
__global__ void k_wt(const float* __restrict__ W_w) {
    int idx = blockIdx.x * 256 + threadIdx.x;     // 64 x 256 = 16384
    int o = idx >> 7, c = idx & 127;
    g_WT[c * 128 + o] = W_w[idx];
}

// ---------------- K1: eA and eB, self-contained (folds vA/vB per-CTA) ----------------
__global__ __launch_bounds__(256)
void k_e(const float* __restrict__ hA, const float* __restrict__ hB,
         const float* __restrict__ WA_w, const float* __restrict__ WA_b,
         const float* __restrict__ aA_w, const float* __restrict__ aA_b,
         const float* __restrict__ WB_w, const float* __restrict__ WB_b,
         const float* __restrict__ aB_w, const float* __restrict__ aB_b) {
    __shared__ float vs[HH * 128];
    __shared__ float ccs[HH];
    int t = threadIdx.x;
    bool isA = blockIdx.x < 256;
    const float* x  = isA ? hA : hB;
    const float* Ww = isA ? WA_w : WB_w;
    const float* Wb = isA ? WA_b : WB_b;
    const float* aw = isA ? aA_w : aB_w;
    const float* ab = isA ? aA_b : aB_b;

    #pragma unroll
    for (int j = 0; j < 4; j++) {
        int idx = t + j * 256;                    // (h,i)
        int h = idx >> 7, i = idx & 127;
        float s = 0.f;
        #pragma unroll
        for (int d = 0; d < 16; d++)
            s += Ww[(h * 128 + i) * 16 + d] * aw[h * 16 + d];
        vs[idx] = s;
    }
    if (t < HH) {
        float c = ab[t];
        #pragma unroll
        for (int d = 0; d < 16; d++)
            c += Wb[t * 16 + d] * aw[t * 16 + d];
        ccs[t] = c;
    }
    __syncthreads();

    int li = (blockIdx.x & 255) * 256 + t;        // 0..65535
    int h = li & 7;
    int row = li >> 3;                            // b*2048 + (n or m)
    const float4* xr = (const float4*)(x + (size_t)row * 128);
    const float4* vr = (const float4*)(vs + h * 128);
    float e = ccs[h];
    #pragma unroll
    for (int q = 0; q < 32; q++) {
        float4 a = xr[q], b = vr[q];
        e += a.x * b.x + a.y * b.y + a.z * b.z + a.w * b.w;
    }
    e *= LOG2E;
    if (isA) {
        g_eA[li] = e;
    } else {
        int b = row >> 11, m = row & 2047;
        g_eB[((b * 8 + h) << 11) + m] = e;
    }
}

// ---------------- K2: z_B = h_B @ Wc + bias ----------------
#define ZB_SMEM ((128 * 128 + 32 * 128) * 4)   // 80 KB
__global__ __launch_bounds__(256, 2)
void k_zB(const float* __restrict__ hB, const float* __restrict__ WB_w,
          const float* __restrict__ WB_b) {
    extern __shared__ float sm[];
    float* Wc = sm;                 // [i*128 + (h*16+d)]
    float* xs = sm + 128 * 128;     // [r*128 + i]
    int t = threadIdx.x;
    int row0 = blockIdx.x * 32;

    for (int idx = t; idx < 16384; idx += 256) {
        int h = idx >> 11, i = (idx >> 4) & 127, d = idx & 15;
        Wc[i * 128 + h * 16 + d] = WB_w[idx];
    }
    {
        const float4* src = (const float4*)(hB + (size_t)row0 * 128);
        #pragma unroll
        for (int j = 0; j < 4; j++)
            ((float4*)xs)[t + j * 256] = src[t + j * 256];
    }
    __syncthreads();

    int c = t & 127, rg = t >> 7;
    float acc[16];
    #pragma unroll
    for (int k = 0; k < 16; k++) acc[k] = 0.f;

    for (int i = 0; i < 128; i += 4) {
        float w0 = Wc[i * 128 + c];
        float w1 = Wc[(i + 1) * 128 + c];
        float w2 = Wc[(i + 2) * 128 + c];
        float w3 = Wc[(i + 3) * 128 + c];
        #pragma unroll
        for (int k = 0; k < 16; k++) {
            int r = rg * 16 + k;
            float4 x4 = *(const float4*)&xs[r * 128 + i];
            acc[k] += x4.x * w0 + x4.y * w1 + x4.z * w2 + x4.w * w3;
        }
    }
    float bias = WB_b[c];
    #pragma unroll
    for (int k = 0; k < 16; k++) {
        int r = rg * 16 + k;
        g_zB[(size_t)(row0 + r) * 128 + c] = acc[k] + bias;
    }
}

// ---------------- K4: fused masked softmax-attention + output GEMM ----------------
// CTA = 16 rows x 8 heads = 128 threads; grid 128x4 = 512 CTAs (single wave)
// smem: zB_s 8192 f | eB_t 512 f | mp_s 16 u64 ; cat_s aliases zB_s (16*129)
#define MAIN_SMEM ((8192 + 512) * 4 + 16 * 8)
__global__ __launch_bounds__(128, 4)
void k_main(const int* __restrict__ mask, const float* __restrict__ W_b,
            float* __restrict__ out) {
    extern __shared__ float sm[];
    float* zB_s = sm;                        // 8192
    float* eB_t = sm + 8192;                 // 512: [h][64]
    ull*   mp_s = (ull*)(eB_t + 512);        // 16
    float* cat_s = zB_s;                     // alias: 16*129 floats

    int t = threadIdx.x;
    int lane = t & 15;                       // row within tile
    int h = t >> 4;                          // head
    int b = blockIdx.y;
    int n0 = blockIdx.x * 16;
    int rowA = b * NA + n0;

    float ea = g_eA[(size_t)(rowA + lane) * 8 + h];
    ull acc[8];
    #pragma unroll
    for (int k = 0; k < 8; k++) acc[k] = 0ULL;
    float Z = 0.f;

    const int sn = t >> 3, sj = t & 7;       // mask staging: 16 rows x 8 qwords
    const int* mbase = mask + ((size_t)(b * NA + n0 + sn)) * (size_t)NBB;
    const float* eBrow = g_eB + ((size_t)b * 8) * 2048;   // + h*2048 + m

    for (int m0 = 0; m0 < NBB; m0 += 64) {
        __syncthreads();
        // stage zB tile (64 rows x 128 f = 2048 float4), 16 per thread
        {
            const float4* src = (const float4*)(g_zB + (size_t)(b * NBB + m0) * 128);
            #pragma unroll
            for (int j = 0; j < 16; j++)
                ((float4*)zB_s)[t + j * 128] = src[t + j * 128];
        }
        // stage eB tile: [h][64], 4 per thread
        {
            #pragma unroll
            for (int j = 0; j < 4; j++) {
                int idx = t + j * 128;
                int hh = idx >> 6, mm = idx & 63;
                eB_t[idx] = eBrow[hh * 2048 + m0 + mm];
            }
        }
        // pack mask (int32 0/1): 16 rows x 64 bits, 1 byte per thread
        {
            const int4* mp4 = (const int4*)(mbase + m0 + sj * 8);
            int4 a = mp4[0], c = mp4[1];
            unsigned int bits =
                  (unsigned int)(a.x != 0)
                | ((unsigned int)(a.y != 0) << 1)
                | ((unsigned int)(a.z != 0) << 2)
                | ((unsigned int)(a.w != 0) << 3)
                | ((unsigned int)(c.x != 0) << 4)
                | ((unsigned int)(c.y != 0) << 5)
                | ((unsigned int)(c.z != 0) << 6)
                | ((unsigned int)(c.w != 0) << 7);
            ((unsigned char*)mp_s)[sn * 8 + sj] = (unsigned char)bits;
        }
        __syncthreads();

        ull mb = mp_s[lane];
        const float* ebh = eB_t + h * 64;
        #pragma unroll 8
        for (int m = 0; m < 64; m += 2) {
            float2 ebp = *(const float2*)&ebh[m];
            float e0 = ea + ebp.x;
            float e1 = ea + ebp.y;
            float le0 = fmaxf(e0, 0.01f * e0);
            float le1 = fmaxf(e1, 0.01f * e1);
            float w0, w1;
            asm("ex2.approx.f32 %0, %1;" : "=f"(w0) : "f"(le0));
            asm("ex2.approx.f32 %0, %1;" : "=f"(w1) : "f"(le1));
            w0 = ((mb >> m) & 1ULL) ? w0 : 0.f;
            w1 = ((mb >> (m + 1)) & 1ULL) ? w1 : 0.f;
            Z += w0; Z += w1;
            ull wd0, wd1;
            PACK2(wd0, w0, w0);
            PACK2(wd1, w1, w1);
            const ulonglong2* z0 = (const ulonglong2*)(zB_s + m * 128 + h * 16);
            const ulonglong2* z1 = (const ulonglong2*)(zB_s + (m + 1) * 128 + h * 16);
            ulonglong2 q0 = z0[0], q1 = z0[1];
            ulonglong2 r0 = z1[0], r1 = z1[1];
            FMA2(acc[0], wd0, q0.x); FMA2(acc[1], wd0, q0.y);
            FMA2(acc[2], wd0, q1.x); FMA2(acc[3], wd0, q1.y);
            FMA2(acc[0], wd1, r0.x); FMA2(acc[1], wd1, r0.y);
            FMA2(acc[2], wd1, r1.x); FMA2(acc[3], wd1, r1.y);
            ulonglong2 q2 = z0[2], q3 = z0[3];
            ulonglong2 r2 = z1[2], r3 = z1[3];
            FMA2(acc[4], wd0, q2.x); FMA2(acc[5], wd0, q2.y);
            FMA2(acc[6], wd0, q3.x); FMA2(acc[7], wd0, q3.y);
            FMA2(acc[4], wd1, r2.x); FMA2(acc[5], wd1, r2.y);
            FMA2(acc[6], wd1, r3.x); FMA2(acc[7], wd1, r3.y);
        }
    }
    __syncthreads();

    float inv = 1.f / Z;
    #pragma unroll
    for (int k = 0; k < 8; k++) {
        float lo, hi;
        UNPACK2(lo, hi, acc[k]);
        cat_s[lane * 129 + h * 16 + 2 * k]     = lo * inv;
        cat_s[lane * 129 + h * 16 + 2 * k + 1] = hi * inv;
    }
    __syncthreads();

    // epilogue: out[n,o] = sum_c cat[n,c] * W_T[c,o] + W_b[o], o in [h*16, h*16+16)
    float acc2[16];
    {
        const float4* wb4 = (const float4*)(W_b + h * 16);
        float4 b0 = __ldg(wb4), b1 = __ldg(wb4 + 1), b2 = __ldg(wb4 + 2), b3 = __ldg(wb4 + 3);
        acc2[0]  = b0.x; acc2[1]  = b0.y; acc2[2]  = b0.z; acc2[3]  = b0.w;
        acc2[4]  = b1.x; acc2[5]  = b1.y; acc2[6]  = b1.z; acc2[7]  = b1.w;
        acc2[8]  = b2.x; acc2[9]  = b2.y; acc2[10] = b2.z; acc2[11] = b2.w;
        acc2[12] = b3.x; acc2[13] = b3.y; acc2[14] = b3.z; acc2[15] = b3.w;
    }
    for (int c = 0; c < 128; c++) {
        float x = cat_s[lane * 129 + c];
        const float4* w4 = (const float4*)(g_WT + c * 128 + h * 16);
        float4 w0 = __ldg(w4), w1 = __ldg(w4 + 1), w2 = __ldg(w4 + 2), w3 = __ldg(w4 + 3);
        acc2[0]  += x * w0.x; acc2[1]  += x * w0.y; acc2[2]  += x * w0.z; acc2[3]  += x * w0.w;
        acc2[4]  += x * w1.x; acc2[5]  += x * w1.y; acc2[6]  += x * w1.z; acc2[7]  += x * w1.w;
        acc2[8]  += x * w2.x; acc2[9]  += x * w2.y; acc2[10] += x * w2.z; acc2[11] += x * w2.w;
        acc2[12] += x * w3.x; acc2[13] += x * w3.y; acc2[14] += x * w3.z; acc2[15] += x * w3.w;
    }
    float4* o4 = (float4*)(out + (size_t)(rowA + lane) * 128 + h * 16);
    o4[0] = make_float4(acc2[0],  acc2[1],  acc2[2],  acc2[3]);
    o4[1] = make_float4(acc2[4],  acc2[5],  acc2[6],  acc2[7]);
    o4[2] = make_float4(acc2[8],  acc2[9],  acc2[10], acc2[11]);
    o4[3] = make_float4(acc2[12], acc2[13], acc2[14], acc2[15]);
}

// ---------------- launcher ----------------
extern "C" void kernel_launch(void* const* d_in, const int* in_sizes, int n_in,
                              void* d_out, int out_size) {
    (void)in_sizes; (void)n_in; (void)out_size;
    const float* h_A  = (const float*)d_in[0];
    const float* h_B  = (const float*)d_in[1];
    const int*   mask = (const int*)d_in[2];
    const float* WA_w = (const float*)d_in[3];
    const float* WA_b = (const float*)d_in[4];
    const float* WB_w = (const float*)d_in[5];
    const float* WB_b = (const float*)d_in[6];
    const float* aA_w = (const float*)d_in[7];
    const float* aA_b = (const float*)d_in[8];
    const float* aB_w = (const float*)d_in[9];
    const float* aB_b = (const float*)d_in[10];
    const float* W_w  = (const float*)d_in[11];
    const float* W_b  = (const float*)d_in[12];
    float* out = (float*)d_out;

    cudaFuncSetAttribute(k_zB,   cudaFuncAttributeMaxDynamicSharedMemorySize, ZB_SMEM);
    cudaFuncSetAttribute(k_main, cudaFuncAttributeMaxDynamicSharedMemorySize, MAIN_SMEM);

    k_wt<<<64, 256>>>(W_w);
    k_e<<<512, 256>>>(h_A, h_B, WA_w, WA_b, aA_w, aA_b, WB_w, WB_b, aB_w, aB_b);
    k_zB<<<256, 256, ZB_SMEM>>>(h_B, WB_w, WB_b);
    k_main<<<dim3(128, 4), 128, MAIN_SMEM>>>(mask, W_b, out);
}

// round 5
// speedup vs baseline: 1.7261x; 1.7261x over previous
#include <cuda_runtime.h>

#define BB   4
#define NA   2048
#define NBB  2048
#define HH   8
#define LOG2E 1.44269504088896340736f

typedef unsigned long long ull;

#define FMA2(d, a, b) asm("fma.rn.f32x2 %0, %1, %2, %0;" : "+l"(d) : "l"(a), "l"(b))
#define PACK2(d, lo, hi) asm("mov.b64 %0, {%1, %2};" : "=l"(d) : "f"(lo), "f"(hi))
#define UNPACK2(lo, hi, s) asm("mov.b64 {%0, %1}, %2;" : "=f"(lo), "=f"(hi) : "l"(s))

// ---------------- scratch (static device allocs only) ----------------
__device__ float g_zB[BB * NBB * 128];      // (b, m, h*16+d)
__device__ float g_eA[BB * NA * HH];        // (b*NA+n)*8 + h   (pre-scaled by LOG2E)
__device__ float g_eB[BB * HH * NBB];       // (b*8+h)*2048 + m (pre-scaled by LOG2E)
__device__ float g_vA[HH * 128];
__device__ float g_vB[HH * 128];
__device__ float g_cA[HH];
__device__ float g_cB[HH];
__device__ float g_WT[128 * 128];           // W_T[c*128+o] = W_w[o*128+c]
__device__ float g_Pacc[2 * BB * NA * HH * 16];   // [s][(b*2048+n)][h][16]
__device__ float g_PZ[2 * BB * NA * HH];          // [s][(b*2048+n)*8+h]

// ---------------- K0: fold attention vectors + transpose W ----------------
__global__ void k_prep(const float* __restrict__ WA_w, const float* __restrict__ WA_b,
                       const float* __restrict__ aA_w, const float* __restrict__ aA_b,
                       const float* __restrict__ WB_w, const float* __restrict__ WB_b,
                       const float* __restrict__ aB_w, const float* __restrict__ aB_b,
                       const float* __restrict__ W_w) {
    int t = threadIdx.x;
    for (int idx = t; idx < HH * 128; idx += 256) {
        int h = idx >> 7, i = idx & 127;
        float sA = 0.f, sB = 0.f;
        #pragma unroll
        for (int d = 0; d < 16; d++) {
            sA += WA_w[(h * 128 + i) * 16 + d] * aA_w[h * 16 + d];
            sB += WB_w[(h * 128 + i) * 16 + d] * aB_w[h * 16 + d];
        }
        g_vA[idx] = sA;
        g_vB[idx] = sB;
    }
    if (t < HH) {
        float cA = aA_b[t], cB = aB_b[t];
        #pragma unroll
        for (int d = 0; d < 16; d++) {
            cA += WA_b[t * 16 + d] * aA_w[t * 16 + d];
            cB += WB_b[t * 16 + d] * aB_w[t * 16 + d];
        }
        g_cA[t] = cA;
        g_cB[t] = cB;
    }
    for (int idx = t; idx < 128 * 128; idx += 256) {
        int o = idx >> 7, c = idx & 127;
        g_WT[c * 128 + o] = W_w[idx];
    }
}

// ---------------- K1: eA and eB (pre-scaled by LOG2E) ----------------
__global__ void k_e(const float* __restrict__ hA, const float* __restrict__ hB) {
    int idx = blockIdx.x * 256 + threadIdx.x;   // 0 .. 131071
    const int half = BB * NA * HH;              // 65536
    const float* x; const float* v; const float* cc;
    int li;
    bool isA = idx < half;
    if (isA) { li = idx;        x = hA; v = g_vA; cc = g_cA; }
    else     { li = idx - half; x = hB; v = g_vB; cc = g_cB; }
    int h = li & 7;
    int row = li >> 3;                           // b*2048 + (n or m)
    const float4* xr = (const float4*)(x + (size_t)row * 128);
    const float4* vr = (const float4*)(v + h * 128);
    float e = cc[h];
    #pragma unroll
    for (int q = 0; q < 32; q++) {
        float4 a = xr[q], b = vr[q];
        e += a.x * b.x + a.y * b.y + a.z * b.z + a.w * b.w;
    }
    e *= LOG2E;
    if (isA) {
        g_eA[li] = e;
    } else {
        int b = row >> 11, m = row & 2047;
        g_eB[((b * 8 + h) << 11) + m] = e;
    }
}

// ---------------- K2: z_B = h_B @ Wc + bias ----------------
#define ZB_SMEM ((128 * 128 + 32 * 128) * 4)   // 80 KB
__global__ __launch_bounds__(256, 2)
void k_zB(const float* __restrict__ hB, const float* __restrict__ WB_w,
          const float* __restrict__ WB_b) {
    extern __shared__ float sm[];
    float* Wc = sm;                 // [i*128 + (h*16+d)]
    float* xs = sm + 128 * 128;     // [r*128 + i]
    int t = threadIdx.x;
    int row0 = blockIdx.x * 32;

    for (int idx = t; idx < 16384; idx += 256) {
        int h = idx >> 11, i = (idx >> 4) & 127, d = idx & 15;
        Wc[i * 128 + h * 16 + d] = WB_w[idx];
    }
    {
        const float4* src = (const float4*)(hB + (size_t)row0 * 128);
        #pragma unroll
        for (int j = 0; j < 4; j++)
            ((float4*)xs)[t + j * 256] = src[t + j * 256];
    }
    __syncthreads();

    int c = t & 127, rg = t >> 7;
    float acc[16];
    #pragma unroll
    for (int k = 0; k < 16; k++) acc[k] = 0.f;

    for (int i = 0; i < 128; i += 4) {
        float w0 = Wc[i * 128 + c];
        float w1 = Wc[(i + 1) * 128 + c];
        float w2 = Wc[(i + 2) * 128 + c];
        float w3 = Wc[(i + 3) * 128 + c];
        #pragma unroll
        for (int k = 0; k < 16; k++) {
            int r = rg * 16 + k;
            float4 x4 = *(const float4*)&xs[r * 128 + i];
            acc[k] += x4.x * w0 + x4.y * w1 + x4.z * w2 + x4.w * w3;
        }
    }
    float bias = WB_b[c];
    #pragma unroll
    for (int k = 0; k < 16; k++) {
        int r = rg * 16 + k;
        g_zB[(size_t)(row0 + r) * 128 + c] = acc[k] + bias;
    }
}

// ---------------- K4: partial masked softmax-attention (m-split by 2) ----------------
// CTA = 64 rows x 8 heads, 256 threads; warp = head, lanes = rows, each thread 2 rows.
// grid.x = 64: tile = x>>1 (n-tile of 64), s = x&1 (m half). grid.y = b.
// smem: zB_s 8192 f | eB_t 512 f | mp_s 64 ull
#define MAIN_SMEM ((8192 + 512) * 4 + 64 * 8)
__global__ __launch_bounds__(256, 2)
void k_main(const int* __restrict__ mask) {
    extern __shared__ float sm[];
    float* zB_s = sm;                        // 8192
    float* eB_t = sm + 8192;                 // 512: [h][64]
    ull*   mp_s = (ull*)(eB_t + 512);        // 64

    int t = threadIdx.x;
    int lane = t & 31;                       // row within tile (and +32)
    int h = t >> 5;                          // head
    int b = blockIdx.y;
    int tile = blockIdx.x >> 1;
    int s = blockIdx.x & 1;
    int n0 = tile * 64;
    int row0 = b * NA + n0;                  // global row base
    int mlo = s * 1024;

    float ea0 = g_eA[(size_t)(row0 + lane) * 8 + h];
    float ea1 = g_eA[(size_t)(row0 + lane + 32) * 8 + h];
    ull acc0[8], acc1[8];
    #pragma unroll
    for (int k = 0; k < 8; k++) { acc0[k] = 0ULL; acc1[k] = 0ULL; }
    float Z0 = 0.f, Z1 = 0.f;

    const float* eBrow = g_eB + ((size_t)b * 8) * 2048;   // + h*2048 + m

    for (int m0 = mlo; m0 < mlo + 1024; m0 += 64) {
        __syncthreads();
        // stage zB tile (64 rows x 128 f = 2048 float4), 8 per thread
        {
            const float4* src = (const float4*)(g_zB + (size_t)(b * NBB + m0) * 128);
            #pragma unroll
            for (int j = 0; j < 8; j++)
                ((float4*)zB_s)[t + j * 256] = src[t + j * 256];
        }
        // stage eB tile: [h][64]
        {
            int hh = t >> 6, mm = t & 63;
            eB_t[hh * 64 + mm]       = eBrow[hh * 2048 + m0 + mm];
            eB_t[(hh + 4) * 64 + mm] = eBrow[(hh + 4) * 2048 + m0 + mm];
        }
        // pack mask (int32 0/1): 64 rows x 64 bits = 512 bytes, 2 per thread
        {
            #pragma unroll
            for (int j = 0; j < 2; j++) {
                int idx = t + j * 256;
                int rowi = idx >> 3, bytei = idx & 7;
                const int4* mp4 = (const int4*)
                    (mask + ((size_t)(row0 + rowi)) * NBB + m0 + bytei * 8);
                int4 a = mp4[0], c = mp4[1];
                unsigned int bits =
                      (unsigned int)(a.x != 0)
                    | ((unsigned int)(a.y != 0) << 1)
                    | ((unsigned int)(a.z != 0) << 2)
                    | ((unsigned int)(a.w != 0) << 3)
                    | ((unsigned int)(c.x != 0) << 4)
                    | ((unsigned int)(c.y != 0) << 5)
                    | ((unsigned int)(c.z != 0) << 6)
                    | ((unsigned int)(c.w != 0) << 7);
                ((unsigned char*)mp_s)[rowi * 8 + bytei] = (unsigned char)bits;
            }
        }
        __syncthreads();

        ull mb0 = mp_s[lane];
        ull mb1 = mp_s[lane + 32];
        const float* ebh = eB_t + h * 64;
        #pragma unroll 8
        for (int m = 0; m < 64; m += 2) {
            float2 ebp = *(const float2*)&ebh[m];
            float e00 = ea0 + ebp.x, e01 = ea0 + ebp.y;
            float e10 = ea1 + ebp.x, e11 = ea1 + ebp.y;
            float l00 = fmaxf(e00, 0.01f * e00);
            float l01 = fmaxf(e01, 0.01f * e01);
            float l10 = fmaxf(e10, 0.01f * e10);
            float l11 = fmaxf(e11, 0.01f * e11);
            float w00, w01, w10, w11;
            asm("ex2.approx.f32 %0, %1;" : "=f"(w00) : "f"(l00));
            asm("ex2.approx.f32 %0, %1;" : "=f"(w01) : "f"(l01));
            asm("ex2.approx.f32 %0, %1;" : "=f"(w10) : "f"(l10));
            asm("ex2.approx.f32 %0, %1;" : "=f"(w11) : "f"(l11));
            w00 = ((mb0 >> m) & 1ULL) ? w00 : 0.f;
            w01 = ((mb0 >> (m + 1)) & 1ULL) ? w01 : 0.f;
            w10 = ((mb1 >> m) & 1ULL) ? w10 : 0.f;
            w11 = ((mb1 >> (m + 1)) & 1ULL) ? w11 : 0.f;
            Z0 += w00; Z0 += w01;
            Z1 += w10; Z1 += w11;
            ull wd00, wd01, wd10, wd11;
            PACK2(wd00, w00, w00);
            PACK2(wd01, w01, w01);
            PACK2(wd10, w10, w10);
            PACK2(wd11, w11, w11);
            const ulonglong2* z0 = (const ulonglong2*)(zB_s + m * 128 + h * 16);
            const ulonglong2* z1 = (const ulonglong2*)(zB_s + (m + 1) * 128 + h * 16);
            ulonglong2 q0 = z0[0], q1 = z0[1], q2 = z0[2], q3 = z0[3];
            ulonglong2 r0 = z1[0], r1 = z1[1], r2 = z1[2], r3 = z1[3];
            FMA2(acc0[0], wd00, q0.x); FMA2(acc0[1], wd00, q0.y);
            FMA2(acc0[2], wd00, q1.x); FMA2(acc0[3], wd00, q1.y);
            FMA2(acc0[4], wd00, q2.x); FMA2(acc0[5], wd00, q2.y);
            FMA2(acc0[6], wd00, q3.x); FMA2(acc0[7], wd00, q3.y);
            FMA2(acc0[0], wd01, r0.x); FMA2(acc0[1], wd01, r0.y);
            FMA2(acc0[2], wd01, r1.x); FMA2(acc0[3], wd01, r1.y);
            FMA2(acc0[4], wd01, r2.x); FMA2(acc0[5], wd01, r2.y);
            FMA2(acc0[6], wd01, r3.x); FMA2(acc0[7], wd01, r3.y);
            FMA2(acc1[0], wd10, q0.x); FMA2(acc1[1], wd10, q0.y);
            FMA2(acc1[2], wd10, q1.x); FMA2(acc1[3], wd10, q1.y);
            FMA2(acc1[4], wd10, q2.x); FMA2(acc1[5], wd10, q2.y);
            FMA2(acc1[6], wd10, q3.x); FMA2(acc1[7], wd10, q3.y);
            FMA2(acc1[0], wd11, r0.x); FMA2(acc1[1], wd11, r0.y);
            FMA2(acc1[2], wd11, r1.x); FMA2(acc1[3], wd11, r1.y);
            FMA2(acc1[4], wd11, r2.x); FMA2(acc1[5], wd11, r2.y);
            FMA2(acc1[6], wd11, r3.x); FMA2(acc1[7], wd11, r3.y);
        }
    }

    // write partials: [s][(b*2048+n)][h][16] and Z
    {
        size_t base0 = ((size_t)(s * (BB * NA) + row0 + lane) * 8 + h) * 16;
        size_t base1 = ((size_t)(s * (BB * NA) + row0 + lane + 32) * 8 + h) * 16;
        float4* p0 = (float4*)(g_Pacc + base0);
        float4* p1 = (float4*)(g_Pacc + base1);
        #pragma unroll
        for (int k = 0; k < 4; k++) {
            float a, bq, c, d;
            UNPACK2(a, bq, acc0[2 * k]);
            UNPACK2(c, d, acc0[2 * k + 1]);
            p0[k] = make_float4(a, bq, c, d);
            UNPACK2(a, bq, acc1[2 * k]);
            UNPACK2(c, d, acc1[2 * k + 1]);
            p1[k] = make_float4(a, bq, c, d);
        }
        g_PZ[(size_t)(s * (BB * NA) + row0 + lane) * 8 + h] = Z0;
        g_PZ[(size_t)(s * (BB * NA) + row0 + lane + 32) * 8 + h] = Z1;
    }
}

// ---------------- K5: combine partials + normalize + output GEMM ----------------
// CTA = 32 rows x 8 heads = 256 threads; grid (64, 4)
__global__ __launch_bounds__(256)
void k_reduce(const float* __restrict__ W_b, float* __restrict__ out) {
    __shared__ float cat_s[32 * 129];
    int t = threadIdx.x;
    int lane = t & 31;
    int h = t >> 5;
    int b = blockIdx.y;
    int n0 = blockIdx.x * 32;
    int row = b * NA + n0 + lane;

    {
        const float4* p0 = (const float4*)(g_Pacc + ((size_t)row * 8 + h) * 16);
        const float4* p1 = (const float4*)(g_Pacc + ((size_t)(BB * NA + row) * 8 + h) * 16);
        float Z = g_PZ[(size_t)row * 8 + h] + g_PZ[(size_t)(BB * NA + row) * 8 + h];
        float inv = 1.f / Z;
        #pragma unroll
        for (int k = 0; k < 4; k++) {
            float4 a = p0[k], c = p1[k];
            cat_s[lane * 129 + h * 16 + 4 * k]     = (a.x + c.x) * inv;
            cat_s[lane * 129 + h * 16 + 4 * k + 1] = (a.y + c.y) * inv;
            cat_s[lane * 129 + h * 16 + 4 * k + 2] = (a.z + c.z) * inv;
            cat_s[lane * 129 + h * 16 + 4 * k + 3] = (a.w + c.w) * inv;
        }
    }
    __syncthreads();

    float acc2[16];
    {
        const float4* wb4 = (const float4*)(W_b + h * 16);
        float4 b0 = __ldg(wb4), b1 = __ldg(wb4 + 1), b2 = __ldg(wb4 + 2), b3 = __ldg(wb4 + 3);
        acc2[0]  = b0.x; acc2[1]  = b0.y; acc2[2]  = b0.z; acc2[3]  = b0.w;
        acc2[4]  = b1.x; acc2[5]  = b1.y; acc2[6]  = b1.z; acc2[7]  = b1.w;
        acc2[8]  = b2.x; acc2[9]  = b2.y; acc2[10] = b2.z; acc2[11] = b2.w;
        acc2[12] = b3.x; acc2[13] = b3.y; acc2[14] = b3.z; acc2[15] = b3.w;
    }
    for (int c = 0; c < 128; c++) {
        float x = cat_s[lane * 129 + c];
        const float4* w4 = (const float4*)(g_WT + c * 128 + h * 16);
        float4 w0 = __ldg(w4), w1 = __ldg(w4 + 1), w2 = __ldg(w4 + 2), w3 = __ldg(w4 + 3);
        acc2[0]  += x * w0.x; acc2[1]  += x * w0.y; acc2[2]  += x * w0.z; acc2[3]  += x * w0.w;
        acc2[4]  += x * w1.x; acc2[5]  += x * w1.y; acc2[6]  += x * w1.z; acc2[7]  += x * w1.w;
        acc2[8]  += x * w2.x; acc2[9]  += x * w2.y; acc2[10] += x * w2.z; acc2[11] += x * w2.w;
        acc2[12] += x * w3.x; acc2[13] += x * w3.y; acc2[14] += x * w3.z; acc2[15] += x * w3.w;
    }
    float4* o4 = (float4*)(out + (size_t)row * 128 + h * 16);
    o4[0] = make_float4(acc2[0],  acc2[1],  acc2[2],  acc2[3]);
    o4[1] = make_float4(acc2[4],  acc2[5],  acc2[6],  acc2[7]);
    o4[2] = make_float4(acc2[8],  acc2[9],  acc2[10], acc2[11]);
    o4[3] = make_float4(acc2[12], acc2[13], acc2[14], acc2[15]);
}

// ---------------- launcher ----------------
extern "C" void kernel_launch(void* const* d_in, const int* in_sizes, int n_in,
                              void* d_out, int out_size) {
    (void)in_sizes; (void)n_in; (void)out_size;
    const float* h_A  = (const float*)d_in[0];
    const float* h_B  = (const float*)d_in[1];
    const int*   mask = (const int*)d_in[2];
    const float* WA_w = (const float*)d_in[3];
    const float* WA_b = (const float*)d_in[4];
    const float* WB_w = (const float*)d_in[5];
    const float* WB_b = (const float*)d_in[6];
    const float* aA_w = (const float*)d_in[7];
    const float* aA_b = (const float*)d_in[8];
    const float* aB_w = (const float*)d_in[9];
    const float* aB_b = (const float*)d_in[10];
    const float* W_w  = (const float*)d_in[11];
    const float* W_b  = (const float*)d_in[12];
    float* out = (float*)d_out;

    cudaFuncSetAttribute(k_zB,   cudaFuncAttributeMaxDynamicSharedMemorySize, ZB_SMEM);
    cudaFuncSetAttribute(k_main, cudaFuncAttributeMaxDynamicSharedMemorySize, MAIN_SMEM);

    k_prep<<<1, 256>>>(WA_w, WA_b, aA_w, aA_b, WB_w, WB_b, aB_w, aB_b, W_w);
    k_e<<<512, 256>>>(h_A, h_B);
    k_zB<<<256, 256, ZB_SMEM>>>(h_B, WB_w, WB_b);
    k_main<<<dim3(64, 4), 256, MAIN_SMEM>>>(mask);
    k_reduce<<<dim3(64, 4), 256>>>(W_b, out);
}

// round 6
// speedup vs baseline: 1.9091x; 1.1061x over previous
#include <cuda_runtime.h>

#define BB   4
#define NA   2048
#define NBB  2048
#define HH   8
#define LOG2E 1.44269504088896340736f

typedef unsigned long long ull;

#define FMA2(d, a, b) asm("fma.rn.f32x2 %0, %1, %2, %0;" : "+l"(d) : "l"(a), "l"(b))
#define PACK2(d, lo, hi) asm("mov.b64 %0, {%1, %2};" : "=l"(d) : "f"(lo), "f"(hi))
#define UNPACK2(lo, hi, s) asm("mov.b64 {%0, %1}, %2;" : "=f"(lo), "=f"(hi) : "l"(s))

// ---------------- scratch (static device allocs only) ----------------
__device__ float g_zB[BB * NBB * 128];      // (b, m, h*16+d)
__device__ float g_eA[BB * NA * HH];        // (b*NA+n)*8 + h   (pre-scaled by LOG2E)
__device__ float g_eB[BB * HH * NBB];       // (b*8+h)*2048 + m (pre-scaled by LOG2E)
__device__ float g_WT[128 * 128];           // W_T[c*128+o] = W_w[o*128+c]
__device__ float g_Pacc[2 * BB * NA * HH * 16];   // [s][(b*2048+n)][h][16]
__device__ float g_PZ[2 * BB * NA * HH];          // [s][(b*2048+n)*8+h]

// ---------------- K0: transpose W (wide) ----------------
__global__ void k_wt(const float* __restrict__ W_w) {
    int idx = blockIdx.x * 256 + threadIdx.x;     // 64 x 256 = 16384
    int o = idx >> 7, c = idx & 127;
    g_WT[c * 128 + o] = W_w[idx];
}

// ---------------- K1: eA and eB, self-contained (folds vA/vB per-CTA) ----------------
__global__ __launch_bounds__(256)
void k_e(const float* __restrict__ hA, const float* __restrict__ hB,
         const float* __restrict__ WA_w, const float* __restrict__ WA_b,
         const float* __restrict__ aA_w, const float* __restrict__ aA_b,
         const float* __restrict__ WB_w, const float* __restrict__ WB_b,
         const float* __restrict__ aB_w, const float* __restrict__ aB_b) {
    __shared__ float vs[HH * 128];
    __shared__ float ccs[HH];
    int t = threadIdx.x;
    bool isA = blockIdx.x < 256;
    const float* x  = isA ? hA : hB;
    const float* Ww = isA ? WA_w : WB_w;
    const float* Wb = isA ? WA_b : WB_b;
    const float* aw = isA ? aA_w : aB_w;
    const float* ab = isA ? aA_b : aB_b;

    #pragma unroll
    for (int j = 0; j < 4; j++) {
        int idx = t + j * 256;                    // (h,i)
        int h = idx >> 7, i = idx & 127;
        float s = 0.f;
        #pragma unroll
        for (int d = 0; d < 16; d++)
            s += Ww[(h * 128 + i) * 16 + d] * aw[h * 16 + d];
        vs[idx] = s;
    }
    if (t < HH) {
        float c = ab[t];
        #pragma unroll
        for (int d = 0; d < 16; d++)
            c += Wb[t * 16 + d] * aw[t * 16 + d];
        ccs[t] = c;
    }
    __syncthreads();

    int li = (blockIdx.x & 255) * 256 + t;        // 0..65535
    int h = li & 7;
    int row = li >> 3;                            // b*2048 + (n or m)
    const float4* xr = (const float4*)(x + (size_t)row * 128);
    const float4* vr = (const float4*)(vs + h * 128);
    float e = ccs[h];
    #pragma unroll
    for (int q = 0; q < 32; q++) {
        float4 a = xr[q], b = vr[q];
        e += a.x * b.x + a.y * b.y + a.z * b.z + a.w * b.w;
    }
    e *= LOG2E;
    if (isA) {
        g_eA[li] = e;
    } else {
        int b = row >> 11, m = row & 2047;
        g_eB[((b * 8 + h) << 11) + m] = e;
    }
}

// ---------------- K2: z_B = h_B @ Wc + bias ----------------
#define ZB_SMEM ((128 * 128 + 32 * 128) * 4)   // 80 KB
__global__ __launch_bounds__(256, 2)
void k_zB(const float* __restrict__ hB, const float* __restrict__ WB_w,
          const float* __restrict__ WB_b) {
    extern __shared__ float sm[];
    float* Wc = sm;                 // [i*128 + (h*16+d)]
    float* xs = sm + 128 * 128;     // [r*128 + i]
    int t = threadIdx.x;
    int row0 = blockIdx.x * 32;

    for (int idx = t; idx < 16384; idx += 256) {
        int h = idx >> 11, i = (idx >> 4) & 127, d = idx & 15;
        Wc[i * 128 + h * 16 + d] = WB_w[idx];
    }
    {
        const float4* src = (const float4*)(hB + (size_t)row0 * 128);
        #pragma unroll
        for (int j = 0; j < 4; j++)
            ((float4*)xs)[t + j * 256] = src[t + j * 256];
    }
    __syncthreads();

    int c = t & 127, rg = t >> 7;
    float acc[16];
    #pragma unroll
    for (int k = 0; k < 16; k++) acc[k] = 0.f;

    for (int i = 0; i < 128; i += 4) {
        float w0 = Wc[i * 128 + c];
        float w1 = Wc[(i + 1) * 128 + c];
        float w2 = Wc[(i + 2) * 128 + c];
        float w3 = Wc[(i + 3) * 128 + c];
        #pragma unroll
        for (int k = 0; k < 16; k++) {
            int r = rg * 16 + k;
            float4 x4 = *(const float4*)&xs[r * 128 + i];
            acc[k] += x4.x * w0 + x4.y * w1 + x4.z * w2 + x4.w * w3;
        }
    }
    float bias = WB_b[c];
    #pragma unroll
    for (int k = 0; k < 16; k++) {
        int r = rg * 16 + k;
        g_zB[(size_t)(row0 + r) * 128 + c] = acc[k] + bias;
    }
}

// ---------------- K4: partial masked softmax-attention (m-split by 2) ----------------
// CTA = 64 rows x 8 heads, 256 threads; warp = head, lanes = rows, each thread 2 rows.
// grid.x = 64: tile = x>>1 (n-tile of 64), s = x&1 (m half). grid.y = b.
#define MAIN_SMEM ((8192 + 512) * 4 + 64 * 8)
__global__ __launch_bounds__(256, 2)
void k_main(const int* __restrict__ mask) {
    extern __shared__ float sm[];
    float* zB_s = sm;                        // 8192
    float* eB_t = sm + 8192;                 // 512: [h][64]
    ull*   mp_s = (ull*)(eB_t + 512);        // 64

    int t = threadIdx.x;
    int lane = t & 31;                       // row within tile (and +32)
    int h = t >> 5;                          // head
    int b = blockIdx.y;
    int tile = blockIdx.x >> 1;
    int s = blockIdx.x & 1;
    int n0 = tile * 64;
    int row0 = b * NA + n0;                  // global row base
    int mlo = s * 1024;

    float ea0 = g_eA[(size_t)(row0 + lane) * 8 + h];
    float ea1 = g_eA[(size_t)(row0 + lane + 32) * 8 + h];
    ull acc0[8], acc1[8];
    #pragma unroll
    for (int k = 0; k < 8; k++) { acc0[k] = 0ULL; acc1[k] = 0ULL; }
    float Z0 = 0.f, Z1 = 0.f;

    const float* eBrow = g_eB + ((size_t)b * 8) * 2048;   // + h*2048 + m

    for (int m0 = mlo; m0 < mlo + 1024; m0 += 64) {
        __syncthreads();
        // stage zB tile (64 rows x 128 f = 2048 float4), 8 per thread
        {
            const float4* src = (const float4*)(g_zB + (size_t)(b * NBB + m0) * 128);
            #pragma unroll
            for (int j = 0; j < 8; j++)
                ((float4*)zB_s)[t + j * 256] = src[t + j * 256];
        }
        // stage eB tile: [h][64]
        {
            int hh = t >> 6, mm = t & 63;
            eB_t[hh * 64 + mm]       = eBrow[hh * 2048 + m0 + mm];
            eB_t[(hh + 4) * 64 + mm] = eBrow[(hh + 4) * 2048 + m0 + mm];
        }
        // pack mask (int32 0/1): 64 rows x 64 bits = 512 bytes, 2 per thread
        {
            #pragma unroll
            for (int j = 0; j < 2; j++) {
                int idx = t + j * 256;
                int rowi = idx >> 3, bytei = idx & 7;
                const int4* mp4 = (const int4*)
                    (mask + ((size_t)(row0 + rowi)) * NBB + m0 + bytei * 8);
                int4 a = mp4[0], c = mp4[1];
                unsigned int bits =
                      (unsigned int)(a.x != 0)
                    | ((unsigned int)(a.y != 0) << 1)
                    | ((unsigned int)(a.z != 0) << 2)
                    | ((unsigned int)(a.w != 0) << 3)
                    | ((unsigned int)(c.x != 0) << 4)
                    | ((unsigned int)(c.y != 0) << 5)
                    | ((unsigned int)(c.z != 0) << 6)
                    | ((unsigned int)(c.w != 0) << 7);
                ((unsigned char*)mp_s)[rowi * 8 + bytei] = (unsigned char)bits;
            }
        }
        __syncthreads();

        ull mb0 = mp_s[lane];
        ull mb1 = mp_s[lane + 32];
        const float* ebh = eB_t + h * 64;
        #pragma unroll 8
        for (int m = 0; m < 64; m += 2) {
            float2 ebp = *(const float2*)&ebh[m];
            float e00 = ea0 + ebp.x, e01 = ea0 + ebp.y;
            float e10 = ea1 + ebp.x, e11 = ea1 + ebp.y;
            float l00 = fmaxf(e00, 0.01f * e00);
            float l01 = fmaxf(e01, 0.01f * e01);
            float l10 = fmaxf(e10, 0.01f * e10);
            float l11 = fmaxf(e11, 0.01f * e11);
            float w00, w01, w10, w11;
            asm("ex2.approx.f32 %0, %1;" : "=f"(w00) : "f"(l00));
            asm("ex2.approx.f32 %0, %1;" : "=f"(w01) : "f"(l01));
            asm("ex2.approx.f32 %0, %1;" : "=f"(w10) : "f"(l10));
            asm("ex2.approx.f32 %0, %1;" : "=f"(w11) : "f"(l11));
            w00 = ((mb0 >> m) & 1ULL) ? w00 : 0.f;
            w01 = ((mb0 >> (m + 1)) & 1ULL) ? w01 : 0.f;
            w10 = ((mb1 >> m) & 1ULL) ? w10 : 0.f;
            w11 = ((mb1 >> (m + 1)) & 1ULL) ? w11 : 0.f;
            Z0 += w00; Z0 += w01;
            Z1 += w10; Z1 += w11;
            ull wd00, wd01, wd10, wd11;
            PACK2(wd00, w00, w00);
            PACK2(wd01, w01, w01);
            PACK2(wd10, w10, w10);
            PACK2(wd11, w11, w11);
            const ulonglong2* z0 = (const ulonglong2*)(zB_s + m * 128 + h * 16);
            const ulonglong2* z1 = (const ulonglong2*)(zB_s + (m + 1) * 128 + h * 16);
            ulonglong2 q0 = z0[0], q1 = z0[1], q2 = z0[2], q3 = z0[3];
            ulonglong2 r0 = z1[0], r1 = z1[1], r2 = z1[2], r3 = z1[3];
            FMA2(acc0[0], wd00, q0.x); FMA2(acc0[1], wd00, q0.y);
            FMA2(acc0[2], wd00, q1.x); FMA2(acc0[3], wd00, q1.y);
            FMA2(acc0[4], wd00, q2.x); FMA2(acc0[5], wd00, q2.y);
            FMA2(acc0[6], wd00, q3.x); FMA2(acc0[7], wd00, q3.y);
            FMA2(acc0[0], wd01, r0.x); FMA2(acc0[1], wd01, r0.y);
            FMA2(acc0[2], wd01, r1.x); FMA2(acc0[3], wd01, r1.y);
            FMA2(acc0[4], wd01, r2.x); FMA2(acc0[5], wd01, r2.y);
            FMA2(acc0[6], wd01, r3.x); FMA2(acc0[7], wd01, r3.y);
            FMA2(acc1[0], wd10, q0.x); FMA2(acc1[1], wd10, q0.y);
            FMA2(acc1[2], wd10, q1.x); FMA2(acc1[3], wd10, q1.y);
            FMA2(acc1[4], wd10, q2.x); FMA2(acc1[5], wd10, q2.y);
            FMA2(acc1[6], wd10, q3.x); FMA2(acc1[7], wd10, q3.y);
            FMA2(acc1[0], wd11, r0.x); FMA2(acc1[1], wd11, r0.y);
            FMA2(acc1[2], wd11, r1.x); FMA2(acc1[3], wd11, r1.y);
            FMA2(acc1[4], wd11, r2.x); FMA2(acc1[5], wd11, r2.y);
            FMA2(acc1[6], wd11, r3.x); FMA2(acc1[7], wd11, r3.y);
        }
    }

    // write partials: [s][(b*2048+n)][h][16] and Z
    {
        size_t base0 = ((size_t)(s * (BB * NA) + row0 + lane) * 8 + h) * 16;
        size_t base1 = ((size_t)(s * (BB * NA) + row0 + lane + 32) * 8 + h) * 16;
        float4* p0 = (float4*)(g_Pacc + base0);
        float4* p1 = (float4*)(g_Pacc + base1);
        #pragma unroll
        for (int k = 0; k < 4; k++) {
            float a, bq, c, d;
            UNPACK2(a, bq, acc0[2 * k]);
            UNPACK2(c, d, acc0[2 * k + 1]);
            p0[k] = make_float4(a, bq, c, d);
            UNPACK2(a, bq, acc1[2 * k]);
            UNPACK2(c, d, acc1[2 * k + 1]);
            p1[k] = make_float4(a, bq, c, d);
        }
        g_PZ[(size_t)(s * (BB * NA) + row0 + lane) * 8 + h] = Z0;
        g_PZ[(size_t)(s * (BB * NA) + row0 + lane + 32) * 8 + h] = Z1;
    }
}

// ---------------- K5: combine partials + normalize + output GEMM ----------------
// CTA = 32 rows x 8 heads = 256 threads; grid (64, 4)
// smem: W_Ts 16384 f | cat_s 32*129 f
#define RED_SMEM ((16384 + 32 * 129) * 4)
__global__ __launch_bounds__(256)
void k_reduce(const float* __restrict__ W_b, float* __restrict__ out) {
    extern __shared__ float rsm[];
    float* W_Ts = rsm;                  // 16384
    float* cat_s = rsm + 16384;         // 32*129
    int t = threadIdx.x;
    int lane = t & 31;
    int h = t >> 5;
    int b = blockIdx.y;
    int n0 = blockIdx.x * 32;
    int row = b * NA + n0 + lane;

    // stage W_T (coalesced, conflict-free)
    #pragma unroll
    for (int j = 0; j < 16; j++)
        ((float4*)W_Ts)[t + j * 256] = ((const float4*)g_WT)[t + j * 256];

    {
        const float4* p0 = (const float4*)(g_Pacc + ((size_t)row * 8 + h) * 16);
        const float4* p1 = (const float4*)(g_Pacc + ((size_t)(BB * NA + row) * 8 + h) * 16);
        float Z = g_PZ[(size_t)row * 8 + h] + g_PZ[(size_t)(BB * NA + row) * 8 + h];
        float inv = 1.f / Z;
        #pragma unroll
        for (int k = 0; k < 4; k++) {
            float4 a = p0[k], c = p1[k];
            cat_s[lane * 129 + h * 16 + 4 * k]     = (a.x + c.x) * inv;
            cat_s[lane * 129 + h * 16 + 4 * k + 1] = (a.y + c.y) * inv;
            cat_s[lane * 129 + h * 16 + 4 * k + 2] = (a.z + c.z) * inv;
            cat_s[lane * 129 + h * 16 + 4 * k + 3] = (a.w + c.w) * inv;
        }
    }
    __syncthreads();

    float acc2[16];
    {
        const float4* wb4 = (const float4*)(W_b + h * 16);
        float4 b0 = __ldg(wb4), b1 = __ldg(wb4 + 1), b2 = __ldg(wb4 + 2), b3 = __ldg(wb4 + 3);
        acc2[0]  = b0.x; acc2[1]  = b0.y; acc2[2]  = b0.z; acc2[3]  = b0.w;
        acc2[4]  = b1.x; acc2[5]  = b1.y; acc2[6]  = b1.z; acc2[7]  = b1.w;
        acc2[8]  = b2.x; acc2[9]  = b2.y; acc2[10] = b2.z; acc2[11] = b2.w;
        acc2[12] = b3.x; acc2[13] = b3.y; acc2[14] = b3.z; acc2[15] = b3.w;
    }
    for (int c = 0; c < 128; c++) {
        float x = cat_s[lane * 129 + c];
        const float4* w4 = (const float4*)(W_Ts + c * 128 + h * 16);
        float4 w0 = w4[0], w1 = w4[1], w2 = w4[2], w3 = w4[3];
        acc2[0]  += x * w0.x; acc2[1]  += x * w0.y; acc2[2]  += x * w0.z; acc2[3]  += x * w0.w;
        acc2[4]  += x * w1.x; acc2[5]  += x * w1.y; acc2[6]  += x * w1.z; acc2[7]  += x * w1.w;
        acc2[8]  += x * w2.x; acc2[9]  += x * w2.y; acc2[10] += x * w2.z; acc2[11] += x * w2.w;
        acc2[12] += x * w3.x; acc2[13] += x * w3.y; acc2[14] += x * w3.z; acc2[15] += x * w3.w;
    }
    float4* o4 = (float4*)(out + (size_t)row * 128 + h * 16);
    o4[0] = make_float4(acc2[0],  acc2[1],  acc2[2],  acc2[3]);
    o4[1] = make_float4(acc2[4],  acc2[5],  acc2[6],  acc2[7]);
    o4[2] = make_float4(acc2[8],  acc2[9],  acc2[10], acc2[11]);
    o4[3] = make_float4(acc2[12], acc2[13], acc2[14], acc2[15]);
}

// ---------------- launcher ----------------
extern "C" void kernel_launch(void* const* d_in, const int* in_sizes, int n_in,
                              void* d_out, int out_size) {
    (void)in_sizes; (void)n_in; (void)out_size;
    const float* h_A  = (const float*)d_in[0];
    const float* h_B  = (const float*)d_in[1];
    const int*   mask = (const int*)d_in[2];
    const float* WA_w = (const float*)d_in[3];
    const float* WA_b = (const float*)d_in[4];
    const float* WB_w = (const float*)d_in[5];
    const float* WB_b = (const float*)d_in[6];
    const float* aA_w = (const float*)d_in[7];
    const float* aA_b = (const float*)d_in[8];
    const float* aB_w = (const float*)d_in[9];
    const float* aB_b = (const float*)d_in[10];
    const float* W_w  = (const float*)d_in[11];
    const float* W_b  = (const float*)d_in[12];
    float* out = (float*)d_out;

    cudaFuncSetAttribute(k_zB,     cudaFuncAttributeMaxDynamicSharedMemorySize, ZB_SMEM);
    cudaFuncSetAttribute(k_main,   cudaFuncAttributeMaxDynamicSharedMemorySize, MAIN_SMEM);
    cudaFuncSetAttribute(k_reduce, cudaFuncAttributeMaxDynamicSharedMemorySize, RED_SMEM);

    k_wt<<<64, 256>>>(W_w);
    k_e<<<512, 256>>>(h_A, h_B, WA_w, WA_b, aA_w, aA_b, WB_w, WB_b, aB_w, aB_b);
    k_zB<<<256, 256, ZB_SMEM>>>(h_B, WB_w, WB_b);
    k_main<<<dim3(64, 4), 256, MAIN_SMEM>>>(mask);
    k_reduce<<<dim3(64, 4), 256, RED_SMEM>>>(W_b, out);
}

// round 8
// speedup vs baseline: 1.9620x; 1.0277x over previous
#include <cuda_runtime.h>

#define BB   4
#define NA   2048
#define NBB  2048
#define HH   8
#define LOG2E 1.44269504088896340736f

typedef unsigned long long ull;

#define FMA2(d, a, b) asm("fma.rn.f32x2 %0, %1, %2, %0;" : "+l"(d) : "l"(a), "l"(b))
#define PACK2(d, lo, hi) asm("mov.b64 %0, {%1, %2};" : "=l"(d) : "f"(lo), "f"(hi))
#define UNPACK2(lo, hi, s) asm("mov.b64 {%0, %1}, %2;" : "=f"(lo), "=f"(hi) : "l"(s))

// ---------------- scratch (static device allocs only) ----------------
__device__ float  g_zB[BB * NBB * 128];       // (b, m, h*16+d)
__device__ float4 g_eAp[BB * NA * HH];        // [(b*2048+n)*8+h] = (ea, ex2(ea), ex2(.01ea), 0)
__device__ float4 g_eBp[BB * HH * NBB];       // [(b*8+h)*2048+m] = (eb, ex2(eb), ex2(.01eb), 0)
__device__ float  g_WT[128 * 128];            // W_T[c*128+o] = W_w[o*128+c]
__device__ float  g_Pacc[2 * BB * NA * HH * 16];   // [s][(b*2048+n)][h][16]
__device__ float  g_PZ[2 * BB * NA * HH];          // [s][(b*2048+n)*8+h]

// ---------------- K1: eA/eB + exp factors; CTAs >= 512 transpose W ----------------
__global__ __launch_bounds__(256)
void k_e(const float* __restrict__ hA, const float* __restrict__ hB,
         const float* __restrict__ WA_w, const float* __restrict__ WA_b,
         const float* __restrict__ aA_w, const float* __restrict__ aA_b,
         const float* __restrict__ WB_w, const float* __restrict__ WB_b,
         const float* __restrict__ aB_w, const float* __restrict__ aB_b,
         const float* __restrict__ W_w) {
    int t = threadIdx.x;
    int bx = blockIdx.x;
    if (bx >= 512) {                          // W transpose (64 CTAs)
        int idx = (bx - 512) * 256 + t;
        int o = idx >> 7, c = idx & 127;
        g_WT[c * 128 + o] = W_w[idx];
        return;
    }

    __shared__ float vs[HH * 128];
    __shared__ float ccs[HH];
    bool isA = bx < 256;
    const float* x  = isA ? hA : hB;
    const float* Ww = isA ? WA_w : WB_w;
    const float* Wb = isA ? WA_b : WB_b;
    const float* aw = isA ? aA_w : aB_w;
    const float* ab = isA ? aA_b : aB_b;

    #pragma unroll
    for (int j = 0; j < 4; j++) {
        int idx = t + j * 256;                // (h,i)
        int h = idx >> 7, i = idx & 127;
        float s = 0.f;
        #pragma unroll
        for (int d = 0; d < 16; d++)
            s += Ww[(h * 128 + i) * 16 + d] * aw[h * 16 + d];
        vs[idx] = s;
    }
    if (t < HH) {
        float c = ab[t];
        #pragma unroll
        for (int d = 0; d < 16; d++)
            c += Wb[t * 16 + d] * aw[t * 16 + d];
        ccs[t] = c;
    }
    __syncthreads();

    int li = (bx & 255) * 256 + t;            // 0..65535
    int h = li & 7;
    int row = li >> 3;                        // b*2048 + (n or m)
    const float4* xr = (const float4*)(x + (size_t)row * 128);
    const float4* vr = (const float4*)(vs + h * 128);
    float e = ccs[h];
    #pragma unroll
    for (int q = 0; q < 32; q++) {
        float4 a = xr[q], b = vr[q];
        e += a.x * b.x + a.y * b.y + a.z * b.z + a.w * b.w;
    }
    e *= LOG2E;                               // scaled so exp == ex2
    float p0, p1, es = 0.01f * e;
    asm("ex2.approx.f32 %0, %1;" : "=f"(p0) : "f"(e));
    asm("ex2.approx.f32 %0, %1;" : "=f"(p1) : "f"(es));
    if (isA) {
        g_eAp[li] = make_float4(e, p0, p1, 0.f);
    } else {
        int b = row >> 11, m = row & 2047;
        g_eBp[((b * 8 + h) << 11) + m] = make_float4(e, p0, p1, 0.f);
    }
}

// ---------------- K2: z_B = h_B @ Wc + bias ----------------
#define ZB_SMEM ((128 * 128 + 32 * 128) * 4)   // 80 KB
__global__ __launch_bounds__(256, 2)
void k_zB(const float* __restrict__ hB, const float* __restrict__ WB_w,
          const float* __restrict__ WB_b) {
    extern __shared__ float sm[];
    float* Wc = sm;                 // [i*128 + (h*16+d)]
    float* xs = sm + 128 * 128;     // [r*128 + i]
    int t = threadIdx.x;
    int row0 = blockIdx.x * 32;

    for (int idx = t; idx < 16384; idx += 256) {
        int h = idx >> 11, i = (idx >> 4) & 127, d = idx & 15;
        Wc[i * 128 + h * 16 + d] = WB_w[idx];
    }
    {
        const float4* src = (const float4*)(hB + (size_t)row0 * 128);
        #pragma unroll
        for (int j = 0; j < 4; j++)
            ((float4*)xs)[t + j * 256] = src[t + j * 256];
    }
    __syncthreads();

    int c = t & 127, rg = t >> 7;
    float acc[16];
    #pragma unroll
    for (int k = 0; k < 16; k++) acc[k] = 0.f;

    for (int i = 0; i < 128; i += 4) {
        float w0 = Wc[i * 128 + c];
        float w1 = Wc[(i + 1) * 128 + c];
        float w2 = Wc[(i + 2) * 128 + c];
        float w3 = Wc[(i + 3) * 128 + c];
        #pragma unroll
        for (int k = 0; k < 16; k++) {
            int r = rg * 16 + k;
            float4 x4 = *(const float4*)&xs[r * 128 + i];
            acc[k] += x4.x * w0 + x4.y * w1 + x4.z * w2 + x4.w * w3;
        }
    }
    float bias = WB_b[c];
    #pragma unroll
    for (int k = 0; k < 16; k++) {
        int r = rg * 16 + k;
        g_zB[(size_t)(row0 + r) * 128 + c] = acc[k] + bias;
    }
}

// ---------------- K4: partial masked softmax-attention, MUFU-free inner loop ----------------
// CTA = 64 rows x 8 heads, 256 threads; warp = head, each thread 2 rows.
// grid.x = 64: tile = x>>1 (n-tile of 64), s = x&1 (m half). grid.y = b.
// smem: zB_s 8192 f | eBp_s 512 float4 | mp_s 64 ull
#define MAIN_SMEM ((8192 + 2048) * 4 + 64 * 8)
__global__ __launch_bounds__(256, 2)
void k_main(const int* __restrict__ mask) {
    extern __shared__ float sm[];
    float*  zB_s  = sm;                       // 8192 f
    float4* eBp_s = (float4*)(sm + 8192);     // 512 float4: [h][64]
    ull*    mp_s  = (ull*)(sm + 8192 + 2048); // 64

    int t = threadIdx.x;
    int lane = t & 31;                        // row within tile (and +32)
    int h = t >> 5;                           // head
    int b = blockIdx.y;
    int tile = blockIdx.x >> 1;
    int s = blockIdx.x & 1;
    int n0 = tile * 64;
    int row0 = b * NA + n0;
    int mlo = s * 1024;

    float4 pa0 = g_eAp[(size_t)(row0 + lane) * 8 + h];      // (ea, p0, p1, -)
    float4 pa1 = g_eAp[(size_t)(row0 + lane + 32) * 8 + h];
    float ea0 = pa0.x, pA00 = pa0.y, pA01 = pa0.z;
    float ea1 = pa1.x, pA10 = pa1.y, pA11 = pa1.z;

    ull acc0[8], acc1[8];
    #pragma unroll
    for (int k = 0; k < 8; k++) { acc0[k] = 0ULL; acc1[k] = 0ULL; }
    float Z0 = 0.f, Z1 = 0.f;

    const float4* eBbase = g_eBp + ((size_t)b * 8) * 2048;  // + h*2048 + m

    for (int m0 = mlo; m0 < mlo + 1024; m0 += 64) {
        __syncthreads();
        // stage zB tile (64 rows x 128 f = 2048 float4), 8 per thread
        {
            const float4* src = (const float4*)(g_zB + (size_t)(b * NBB + m0) * 128);
            #pragma unroll
            for (int j = 0; j < 8; j++)
                ((float4*)zB_s)[t + j * 256] = src[t + j * 256];
        }
        // stage eBp tile: [h][64] float4, 2 per thread
        {
            int hh = t >> 6, mm = t & 63;
            eBp_s[hh * 64 + mm]       = eBbase[(size_t)hh * 2048 + m0 + mm];
            eBp_s[(hh + 4) * 64 + mm] = eBbase[(size_t)(hh + 4) * 2048 + m0 + mm];
        }
        // pack mask (int32 0/1): 64 rows x 64 bits = 512 bytes, 2 per thread
        {
            #pragma unroll
            for (int j = 0; j < 2; j++) {
                int idx = t + j * 256;
                int rowi = idx >> 3, bytei = idx & 7;
                const int4* mp4 = (const int4*)
                    (mask + ((size_t)(row0 + rowi)) * NBB + m0 + bytei * 8);
                int4 a = mp4[0], c = mp4[1];
                unsigned int bits =
                      (unsigned int)(a.x != 0)
                    | ((unsigned int)(a.y != 0) << 1)
                    | ((unsigned int)(a.z != 0) << 2)
                    | ((unsigned int)(a.w != 0) << 3)
                    | ((unsigned int)(c.x != 0) << 4)
                    | ((unsigned int)(c.y != 0) << 5)
                    | ((unsigned int)(c.z != 0) << 6)
                    | ((unsigned int)(c.w != 0) << 7);
                ((unsigned char*)mp_s)[rowi * 8 + bytei] = (unsigned char)bits;
            }
        }
        __syncthreads();

        ull mb0 = mp_s[lane];
        ull mb1 = mp_s[lane + 32];
        const float4* ebh = eBp_s + h * 64;
        #pragma unroll 8
        for (int m = 0; m < 64; m++) {
            float4 eb = ebh[m];                         // (eb, pB0, pB1, -)
            float e0 = ea0 + eb.x;
            float e1 = ea1 + eb.x;
            float w0 = (e0 >= 0.f) ? (pA00 * eb.y) : (pA01 * eb.z);
            float w1 = (e1 >= 0.f) ? (pA10 * eb.y) : (pA11 * eb.z);
            w0 = ((mb0 >> m) & 1ULL) ? w0 : 0.f;
            w1 = ((mb1 >> m) & 1ULL) ? w1 : 0.f;
            Z0 += w0;
            Z1 += w1;
            ull wd0, wd1;
            PACK2(wd0, w0, w0);
            PACK2(wd1, w1, w1);
            const ulonglong2* z = (const ulonglong2*)(zB_s + m * 128 + h * 16);
            ulonglong2 q0 = z[0], q1 = z[1], q2 = z[2], q3 = z[3];
            FMA2(acc0[0], wd0, q0.x); FMA2(acc0[1], wd0, q0.y);
            FMA2(acc0[2], wd0, q1.x); FMA2(acc0[3], wd0, q1.y);
            FMA2(acc0[4], wd0, q2.x); FMA2(acc0[5], wd0, q2.y);
            FMA2(acc0[6], wd0, q3.x); FMA2(acc0[7], wd0, q3.y);
            FMA2(acc1[0], wd1, q0.x); FMA2(acc1[1], wd1, q0.y);
            FMA2(acc1[2], wd1, q1.x); FMA2(acc1[3], wd1, q1.y);
            FMA2(acc1[4], wd1, q2.x); FMA2(acc1[5], wd1, q2.y);
            FMA2(acc1[6], wd1, q3.x); FMA2(acc1[7], wd1, q3.y);
        }
    }

    // write partials: [s][(b*2048+n)][h][16] and Z
    {
        size_t base0 = ((size_t)(s * (BB * NA) + row0 + lane) * 8 + h) * 16;
        size_t base1 = ((size_t)(s * (BB * NA) + row0 + lane + 32) * 8 + h) * 16;
        float4* p0 = (float4*)(g_Pacc + base0);
        float4* p1 = (float4*)(g_Pacc + base1);
        #pragma unroll
        for (int k = 0; k < 4; k++) {
            float a, bq, c, d;
            UNPACK2(a, bq, acc0[2 * k]);
            UNPACK2(c, d, acc0[2 * k + 1]);
            p0[k] = make_float4(a, bq, c, d);
            UNPACK2(a, bq, acc1[2 * k]);
            UNPACK2(c, d, acc1[2 * k + 1]);
            p1[k] = make_float4(a, bq, c, d);
        }
        g_PZ[(size_t)(s * (BB * NA) + row0 + lane) * 8 + h] = Z0;
        g_PZ[(size_t)(s * (BB * NA) + row0 + lane + 32) * 8 + h] = Z1;
    }
}

// ---------------- K5: combine partials + normalize + output GEMM ----------------
#define RED_SMEM ((16384 + 32 * 129) * 4)
__global__ __launch_bounds__(256)
void k_reduce(const float* __restrict__ W_b, float* __restrict__ out) {
    extern __shared__ float rsm[];
    float* W_Ts = rsm;                  // 16384
    float* cat_s = rsm + 16384;         // 32*129
    int t = threadIdx.x;
    int lane = t & 31;
    int h = t >> 5;
    int b = blockIdx.y;
    int n0 = blockIdx.x * 32;
    int row = b * NA + n0 + lane;

    #pragma unroll
    for (int j = 0; j < 16; j++)
        ((float4*)W_Ts)[t + j * 256] = ((const float4*)g_WT)[t + j * 256];

    {
        const float4* p0 = (const float4*)(g_Pacc + ((size_t)row * 8 + h) * 16);
        const float4* p1 = (const float4*)(g_Pacc + ((size_t)(BB * NA + row) * 8 + h) * 16);
        float Z = g_PZ[(size_t)row * 8 + h] + g_PZ[(size_t)(BB * NA + row) * 8 + h];
        float inv = 1.f / Z;
        #pragma unroll
        for (int k = 0; k < 4; k++) {
            float4 a = p0[k], c = p1[k];
            cat_s[lane * 129 + h * 16 + 4 * k]     = (a.x + c.x) * inv;
            cat_s[lane * 129 + h * 16 + 4 * k + 1] = (a.y + c.y) * inv;
            cat_s[lane * 129 + h * 16 + 4 * k + 2] = (a.z + c.z) * inv;
            cat_s[lane * 129 + h * 16 + 4 * k + 3] = (a.w + c.w) * inv;
        }
    }
    __syncthreads();

    float acc2[16];
    {
        const float4* wb4 = (const float4*)(W_b + h * 16);
        float4 b0 = __ldg(wb4), b1 = __ldg(wb4 + 1), b2 = __ldg(wb4 + 2), b3 = __ldg(wb4 + 3);
        acc2[0]  = b0.x; acc2[1]  = b0.y; acc2[2]  = b0.z; acc2[3]  = b0.w;
        acc2[4]  = b1.x; acc2[5]  = b1.y; acc2[6]  = b1.z; acc2[7]  = b1.w;
        acc2[8]  = b2.x; acc2[9]  = b2.y; acc2[10] = b2.z; acc2[11] = b2.w;
        acc2[12] = b3.x; acc2[13] = b3.y; acc2[14] = b3.z; acc2[15] = b3.w;
    }
    for (int c = 0; c < 128; c++) {
        float x = cat_s[lane * 129 + c];
        const float4* w4 = (const float4*)(W_Ts + c * 128 + h * 16);
        float4 w0 = w4[0], w1 = w4[1], w2 = w4[2], w3 = w4[3];
        acc2[0]  += x * w0.x; acc2[1]  += x * w0.y; acc2[2]  += x * w0.z; acc2[3]  += x * w0.w;
        acc2[4]  += x * w1.x; acc2[5]  += x * w1.y; acc2[6]  += x * w1.z; acc2[7]  += x * w1.w;
        acc2[8]  += x * w2.x; acc2[9]  += x * w2.y; acc2[10] += x * w2.z; acc2[11] += x * w2.w;
        acc2[12] += x * w3.x; acc2[13] += x * w3.y; acc2[14] += x * w3.z; acc2[15] += x * w3.w;
    }
    float4* o4 = (float4*)(out + (size_t)row * 128 + h * 16);
    o4[0] = make_float4(acc2[0],  acc2[1],  acc2[2],  acc2[3]);
    o4[1] = make_float4(acc2[4],  acc2[5],  acc2[6],  acc2[7]);
    o4[2] = make_float4(acc2[8],  acc2[9],  acc2[10], acc2[11]);
    o4[3] = make_float4(acc2[12], acc2[13], acc2[14], acc2[15]);
}

// ---------------- launcher ----------------
extern "C" void kernel_launch(void* const* d_in, const int* in_sizes, int n_in,
                              void* d_out, int out_size) {
    (void)in_sizes; (void)n_in; (void)out_size;
    const float* h_A  = (const float*)d_in[0];
    const float* h_B  = (const float*)d_in[1];
    const int*   mask = (const int*)d_in[2];
    const float* WA_w = (const float*)d_in[3];
    const float* WA_b = (const float*)d_in[4];
    const float* WB_w = (const float*)d_in[5];
    const float* WB_b = (const float*)d_in[6];
    const float* aA_w = (const float*)d_in[7];
    const float* aA_b = (const float*)d_in[8];
    const float* aB_w = (const float*)d_in[9];
    const float* aB_b = (const float*)d_in[10];
    const float* W_w  = (const float*)d_in[11];
    const float* W_b  = (const float*)d_in[12];
    float* out = (float*)d_out;

    cudaFuncSetAttribute(k_zB,     cudaFuncAttributeMaxDynamicSharedMemorySize, ZB_SMEM);
    cudaFuncSetAttribute(k_main,   cudaFuncAttributeMaxDynamicSharedMemorySize, MAIN_SMEM);
    cudaFuncSetAttribute(k_reduce, cudaFuncAttributeMaxDynamicSharedMemorySize, RED_SMEM);

    k_e<<<576, 256>>>(h_A, h_B, WA_w, WA_b, aA_w, aA_b, WB_w, WB_b, aB_w, aB_b, W_w);
    k_zB<<<256, 256, ZB_SMEM>>>(h_B, WB_w, WB_b);
    k_main<<<dim3(64, 4), 256, MAIN_SMEM>>>(mask);
    k_reduce<<<dim3(64, 4), 256, RED_SMEM>>>(W_b, out);
}